// round 15
// baseline (speedup 1.0000x reference)
#include <cuda_runtime.h>
#include <cuda_fp16.h>
#include <stdint.h>

#define BB 4
#define LL 4096
#define DD 1024
#define DKK 64
#define BL (BB * LL)

// Projected operands, single fp16.
// q/k: [token][64] row-major (q pre-scaled by 0.125*log2e). v: [dk][token].
__device__ __half g_q[(size_t)BL * 64];
__device__ __half g_k[(size_t)BL * 64];
__device__ __half g_v[(size_t)64 * BL];
// Pre-converted weights fp16: [which][n][k], k contiguous.
__device__ __half g_w[3 * 64 * 1024];

// ---------------------------------------------------------------------------
// helpers
// ---------------------------------------------------------------------------
__device__ __forceinline__ uint32_t smem_u32(const void* p) {
  uint32_t a;
  asm("{ .reg .u64 t; cvta.to.shared.u64 t, %1; cvt.u32.u64 %0, t; }"
      : "=r"(a) : "l"(p));
  return a;
}
__device__ __forceinline__ void sts128(uint32_t a, uint4 v) {
  asm volatile("st.shared.v4.b32 [%0], {%1,%2,%3,%4};" ::"r"(a), "r"(v.x),
               "r"(v.y), "r"(v.z), "r"(v.w));
}
__device__ __forceinline__ float2 lds64f(uint32_t a) {
  float2 v;
  asm volatile("ld.shared.v2.f32 {%0,%1}, [%2];" : "=f"(v.x), "=f"(v.y)
               : "r"(a));
  return v;
}
__device__ __forceinline__ void cpa16(uint32_t dst, const void* src) {
  asm volatile("cp.async.cg.shared.global [%0], [%1], 16;" ::"r"(dst),
               "l"(__cvta_generic_to_global(src))
               : "memory");
}
#define CP_COMMIT() asm volatile("cp.async.commit_group;" ::: "memory")
#define CP_WAIT0() asm volatile("cp.async.wait_group 0;" ::: "memory")
#define CP_WAIT1() asm volatile("cp.async.wait_group 1;" ::: "memory")

__device__ __forceinline__ void ldmx4(uint32_t a, uint32_t& r0, uint32_t& r1,
                                      uint32_t& r2, uint32_t& r3) {
  asm volatile("ldmatrix.sync.aligned.m8n8.x4.shared.b16 {%0,%1,%2,%3}, [%4];"
               : "=r"(r0), "=r"(r1), "=r"(r2), "=r"(r3) : "r"(a));
}
__device__ __forceinline__ void ldmx2(uint32_t a, uint32_t& r0, uint32_t& r1) {
  asm volatile("ldmatrix.sync.aligned.m8n8.x2.shared.b16 {%0,%1}, [%2];"
               : "=r"(r0), "=r"(r1) : "r"(a));
}
__device__ __forceinline__ void mma16816(float c[4], const uint32_t a[4],
                                         const uint32_t b0, const uint32_t b1) {
  asm volatile(
      "mma.sync.aligned.m16n8k16.row.col.f32.f16.f16.f32 "
      "{%0,%1,%2,%3}, {%4,%5,%6,%7}, {%8,%9}, {%0,%1,%2,%3};"
      : "+f"(c[0]), "+f"(c[1]), "+f"(c[2]), "+f"(c[3])
      : "r"(a[0]), "r"(a[1]), "r"(a[2]), "r"(a[3]), "r"(b0), "r"(b1));
}
__device__ __forceinline__ float ex2(float x) {
  float r;
  asm("ex2.approx.f32 %0, %1;" : "=f"(r) : "f"(x));
  return r;
}
// pack two floats into fp16x2 (x0 low, x1 high).
__device__ __forceinline__ uint32_t pkhf(float x0, float x1) {
  __half2 h = __floats2half2_rn(x0, x1);
  return *(uint32_t*)&h;
}

// ---------------------------------------------------------------------------
// Weight pre-convert: W[which][k][n] fp32 -> g_w [which][n][k] fp16.
// ---------------------------------------------------------------------------
__global__ __launch_bounds__(256) void wconv(const float* __restrict__ Wq,
                                             const float* __restrict__ Wk,
                                             const float* __restrict__ Wv) {
  __shared__ float tile[16][65];
  const int which = blockIdx.x >> 6;
  const int k0 = (blockIdx.x & 63) * 16;
  const float* W = (which == 0) ? Wq : (which == 1) ? Wk : Wv;
  const int tid = threadIdx.x;
#pragma unroll
  for (int i = 0; i < 4; i++) {
    int id = tid + 256 * i;  // 0..1023
    int kk = id >> 6, n = id & 63;
    tile[kk][n] = W[(size_t)(k0 + kk) * DKK + n];
  }
  __syncthreads();
#pragma unroll
  for (int i = 0; i < 4; i++) {
    int id = tid + 256 * i;
    int n = id >> 4, kk = id & 15;
    g_w[which * 65536 + n * 1024 + k0 + kk] = __float2half(tile[kk][n]);
  }
}

// ---------------------------------------------------------------------------
// FUSED projection, 256 threads (8 warps = 4 m-groups x 2 n-halves).
// q/k/v[m,n] = X_w[m,:]·W_w[:,n] + b_w.  Each X read once.
// Grid 256: CTA = 64 token rows; warp tile 16m x 32n per which.
// Double buffer, prefetch 1 (wait0 -> sync -> issue -> compute).
// Stage = 3 X tiles (64x144 B fp32) + 3 W tiles (64x80 B fp16) = 43008.
// ---------------------------------------------------------------------------
#define PXS 9216
#define PWS 5120
#define PSTG (3 * PXS + 3 * PWS)  // 43008
#define P_SMEM (2 * PSTG)         // 86016

__global__ __launch_bounds__(256, 2) void proj_mma(
    const float* __restrict__ Q, const float* __restrict__ K,
    const float* __restrict__ V, const float* __restrict__ bq,
    const float* __restrict__ bk, const float* __restrict__ bv) {
  extern __shared__ __align__(16) char smem[];
  const uint32_t sb = smem_u32(smem);
  const int tid = threadIdx.x, wid = tid >> 5, lane = tid & 31;
  const int wm = wid & 3, wn = wid >> 2;
  const int r = lane >> 2, qd = lane & 3;
  const int g = lane >> 3;  // ldmatrix x4 group
  const int m0 = blockIdx.x * 64;

  const float* Xs[3] = {Q, K, V};
  const float* biases[3] = {bq, bk, bv};

  float acc[3][4][4];
#pragma unroll
  for (int w = 0; w < 3; w++)
#pragma unroll
    for (int nt = 0; nt < 4; nt++)
#pragma unroll
      for (int i = 0; i < 4; i++) acc[w][nt][i] = 0.0f;

  auto stage_load = [&](uint32_t st, int k0) {
#pragma unroll
    for (int i = 0; i < 9; i++) {
      int idx = tid + 256 * i;  // 0..2303
      if (idx < 1536) {
        int w = idx >> 9;
        int id = idx & 511;
        int row = id >> 3, c = id & 7;
        cpa16(st + w * PXS + row * 144 + c * 16,
              Xs[w] + (size_t)(m0 + row) * DD + k0 + c * 4);
      } else {
        int id = idx - 1536;  // 0..767
        int w = id >> 8;
        int rem = id & 255;
        int row = rem >> 2, c = rem & 3;
        cpa16(st + 3 * PXS + w * PWS + row * 80 + c * 16,
              g_w + w * 65536 + row * 1024 + k0 + c * 8);
      }
    }
  };

  stage_load(sb, 0);
  CP_COMMIT();

  for (int kc = 0; kc < 32; kc++) {
    CP_WAIT0();       // stage kc&1 fully landed
    __syncthreads();  // all warps done reading stage (kc+1)&1 from iter kc-1
    if (kc + 1 < 32) {
      stage_load(sb + ((kc + 1) & 1) * PSTG, (kc + 1) * 32);
      CP_COMMIT();
    }
    const uint32_t st = sb + (kc & 1) * PSTG;
#pragma unroll
    for (int ks = 0; ks < 2; ks++) {
#pragma unroll
      for (int w = 0; w < 3; w++) {
        uint32_t ah[4];
        {
          uint32_t a0 =
              st + w * PXS + (wm * 16 + r) * 144 + (ks * 16 + 2 * qd) * 4;
          float2 v0 = lds64f(a0);
          float2 v1 = lds64f(a0 + 8 * 144);
          float2 v2 = lds64f(a0 + 32);
          float2 v3 = lds64f(a0 + 8 * 144 + 32);
          ah[0] = pkhf(v0.x, v0.y);
          ah[1] = pkhf(v1.x, v1.y);
          ah[2] = pkhf(v2.x, v2.y);
          ah[3] = pkhf(v3.x, v3.y);
        }
        // W fragments: one ldmx4 covers two adjacent 8-col n-tiles.
#pragma unroll
        for (int ntp = 0; ntp < 2; ntp++) {
          uint32_t bb = st + 3 * PXS + w * PWS +
                        (wn * 32 + ntp * 16 + (g >> 1) * 8 + (lane & 7)) * 80 +
                        ks * 32 + (g & 1) * 16;
          uint32_t b0, b1, b2, b3;
          ldmx4(bb, b0, b1, b2, b3);
          mma16816(acc[w][2 * ntp], ah, b0, b1);
          mma16816(acc[w][2 * ntp + 1], ah, b2, b3);
        }
      }
    }
  }

  // Epilogue: bias, (scale for q), fp16 store.  Columns wn*32 .. wn*32+31.
  const int tok0 = m0 + wm * 16 + r;
#pragma unroll
  for (int w = 0; w < 3; w++) {
    const float scl = (w == 0) ? 0.125f * 1.4426950408889634f : 1.0f;
    const float* bias = biases[w];
#pragma unroll
    for (int nt = 0; nt < 4; nt++) {
      int c = wn * 32 + nt * 8 + 2 * qd;
      float bz0 = bias[c], bz1 = bias[c + 1];
      float v0 = (acc[w][nt][0] + bz0) * scl;
      float v1 = (acc[w][nt][1] + bz1) * scl;
      float v2 = (acc[w][nt][2] + bz0) * scl;
      float v3 = (acc[w][nt][3] + bz1) * scl;
      if (w < 2) {
        __half* o = (w == 0) ? g_q : g_k;
        *(uint32_t*)&o[(size_t)tok0 * 64 + c] = pkhf(v0, v1);
        *(uint32_t*)&o[(size_t)(tok0 + 8) * 64 + c] = pkhf(v2, v3);
      } else {
        g_v[(size_t)c * BL + tok0] = __float2half(v0);
        g_v[(size_t)(c + 1) * BL + tok0] = __float2half(v1);
        g_v[(size_t)c * BL + tok0 + 8] = __float2half(v2);
        g_v[(size_t)(c + 1) * BL + tok0 + 8] = __float2half(v3);
      }
    }
  }
}

// ---------------------------------------------------------------------------
// Causal flash attention (fp16 HMMA), cp.async 3-stage ring (prefetch 2),
// OCCUPANCY 4.  Grid (128,4) x 128 thr; CTA = ONE 32-row q tile,
// t = 127 - x (LPT).  smem diet: shared ones block (1152 B) instead of
// per-stage ones rows; q bootstraps through stage 2's K region (read to
// regs before stage 2's first overwrite).  Stage = K 64x144 + V 64x144 =
// 18432; total 1152 + 3*18432 = 56448; x4 CTAs = 225.8 KB.
// ---------------------------------------------------------------------------
#define AP 144
#define ONES 0
#define STAGE0 1152
#define ST_V 9216
#define STAGE_STRIDE 18432
#define A_SMEM (1152 + 3 * 18432)  // 56448
#define STG_O 1152
#define STG_L (1152 + 8192)

__device__ __forceinline__ void load_kv_async(uint32_t stg, size_t kt0,
                                              int tid) {
#pragma unroll
  for (int i = 0; i < 8; i++) {
    int idx = tid + 128 * i;  // 0..1023
    int arr = idx >> 9;       // 0: K, 1: V
    int id = idx & 511;
    int rr = id >> 3, c8 = id & 7;
    uint32_t dst = stg + arr * ST_V + rr * AP + c8 * 16;
    const __half* src = (arr == 0) ? (g_k + (kt0 + rr) * 64 + c8 * 8)
                                   : (g_v + (size_t)rr * BL + kt0 + c8 * 8);
    cpa16(dst, src);
  }
}

__global__ __launch_bounds__(128, 4) void attn_mma(float* __restrict__ out) {
  extern __shared__ __align__(16) char smem[];
  const uint32_t sb = smem_u32(smem);
  const int tid = threadIdx.x, wid = tid >> 5, lane = tid & 31;
  const int wm = wid & 1, wn = wid >> 1;
  const int r = lane >> 2, qd = lane & 3;
  const int b = blockIdx.y;
  const int t = 127 - blockIdx.x;  // largest tiles scheduled first (LPT)
  const int jmax = t >> 1;
  const size_t qtok0 = (size_t)b * LL + t * 32;
  const size_t bt0 = (size_t)b * LL;
  const int g = lane >> 3;  // ldmatrix x4 group

  // q tile (32 rows) -> stage 2's K region (consumed into regs before any
  // overwrite; stage 2 is first written by the prefetch issued at j=0).
  const uint32_t qbase = sb + STAGE0 + 2 * STAGE_STRIDE;
#pragma unroll
  for (int i = 0; i < 2; i++) {
    int id = tid + 128 * i;
    int rr = id >> 3, c8 = id & 7;
    sts128(qbase + rr * AP + c8 * 16,
           *(const uint4*)&g_q[(qtok0 + rr) * 64 + c8 * 8]);
  }
  // shared ones block: row 0 = 1.0h x72, rows 1-7 = 0 (lsum column source).
  for (int idx = tid; idx < 8 * 36; idx += 128) {
    int rr = idx / 36, c = idx % 36;
    *(uint32_t*)(smem + ONES + rr * AP + c * 4) =
        (rr == 0) ? 0x3C003C00u : 0u;
  }
  load_kv_async(sb + STAGE0, bt0, tid);
  CP_COMMIT();
  if (jmax >= 1) load_kv_async(sb + STAGE0 + STAGE_STRIDE, bt0 + 64, tid);
  CP_COMMIT();
  __syncthreads();  // q + ones visible

  // q fragments (held in regs all kernel)
  uint32_t qa[4][4];
#pragma unroll
  for (int ks = 0; ks < 4; ks++) {
    uint32_t ab =
        qbase + (wm * 16 + (lane & 15)) * AP + ks * 32 + (lane >> 4) * 16;
    ldmx4(ab, qa[ks][0], qa[ks][1], qa[ks][2], qa[ks][3]);
  }

  float o[9][4];
#pragma unroll
  for (int nt = 0; nt < 9; nt++)
#pragma unroll
    for (int i = 0; i < 4; i++) o[nt][i] = 0.0f;

  auto body = [&](int j, bool diag) {
    const uint32_t stg = sb + STAGE0 + (j % 3) * STAGE_STRIDE;
    const uint32_t sk = stg, sv = stg + ST_V;

    float s[4][4];
#pragma unroll
    for (int nt = 0; nt < 4; nt++)
#pragma unroll
      for (int i = 0; i < 4; i++) s[nt][i] = 0.0f;
#pragma unroll
    for (int ks = 0; ks < 4; ks++) {
#pragma unroll
      for (int ntp = 0; ntp < 2; ntp++) {
        uint32_t bb = sk +
                      (wn * 32 + ntp * 16 + (g >> 1) * 8 + (lane & 7)) * AP +
                      ks * 32 + (g & 1) * 16;
        uint32_t b0, b1, b2, b3;
        ldmx4(bb, b0, b1, b2, b3);
        mma16816(s[2 * ntp], qa[ks], b0, b1);
        mma16816(s[2 * ntp + 1], qa[ks], b2, b3);
      }
    }

    const int rg0 = t * 32 + wm * 16 + r, rg1 = rg0 + 8;
    uint32_t pa[2][4];
#pragma unroll
    for (int nt = 0; nt < 4; nt++) {
      float e0 = ex2(s[nt][0]);
      float e1 = ex2(s[nt][1]);
      float e2 = ex2(s[nt][2]);
      float e3 = ex2(s[nt][3]);
      if (diag) {
        int cg = j * 64 + wn * 32 + nt * 8 + 2 * qd;
        if (cg > rg0) e0 = 0.0f;
        if (cg + 1 > rg0) e1 = 0.0f;
        if (cg > rg1) e2 = 0.0f;
        if (cg + 1 > rg1) e3 = 0.0f;
      }
      int k2 = nt >> 1, h2 = (nt & 1) * 2;
      pa[k2][h2] = pkhf(e0, e1);
      pa[k2][h2 + 1] = pkhf(e2, e3);
    }

#pragma unroll
    for (int k2 = 0; k2 < 2; k2++) {
#pragma unroll
      for (int ntp = 0; ntp < 4; ntp++) {
        uint32_t bb = sv + (ntp * 16 + (g >> 1) * 8 + (lane & 7)) * AP +
                      (wn * 32 + k2 * 16) * 2 + (g & 1) * 16;
        uint32_t b0, b1, b2, b3;
        ldmx4(bb, b0, b1, b2, b3);
        mma16816(o[2 * ntp], pa[k2], b0, b1);
        mma16816(o[2 * ntp + 1], pa[k2], b2, b3);
      }
      // lsum via shared ones block (row 0 = ones, rows 1-7 = zeros)
      uint32_t bb1 = sb + ONES + (lane & 7) * AP + (wn * 32 + k2 * 16) * 2 +
                     ((lane >> 3) & 1) * 16;
      uint32_t c0, c1;
      ldmx2(bb1, c0, c1);
      mma16816(o[8], pa[k2], c0, c1);
    }
  };

  for (int j = 0; j < jmax; j++) {
    CP_WAIT1();       // in-order completion: stage j ready
    __syncthreads();  // all warps past body(j-1) and q-frag reads
    if (j + 2 <= jmax)
      load_kv_async(sb + STAGE0 + ((j + 2) % 3) * STAGE_STRIDE,
                    bt0 + (size_t)(j + 2) * 64, tid);
    CP_COMMIT();  // always commit (possibly empty)
    body(j, false);
  }
  CP_WAIT1();
  __syncthreads();
  CP_COMMIT();
  body(jmax, true);  // diagonal tile, masked
  __syncthreads();   // all compute done; stage smem reusable for epilogue

  // epilogue: combine key-halves via smem; lsum from o[8] (col 0 of ones).
  float ls0 = o[8][0], ls1 = o[8][2];
  float* stgO = (float*)(smem + STG_O);
  float* stgL = (float*)(smem + STG_L);
  if (wn == 1) {
    if (qd == 0) {
      stgL[wm * 16 + r] = ls0;
      stgL[wm * 16 + r + 8] = ls1;
    }
#pragma unroll
    for (int nt = 0; nt < 8; nt++) {
      int c = nt * 8 + 2 * qd;
      *(float2*)&stgO[(wm * 16 + r) * 64 + c] = make_float2(o[nt][0], o[nt][1]);
      *(float2*)&stgO[(wm * 16 + r + 8) * 64 + c] =
          make_float2(o[nt][2], o[nt][3]);
    }
  }
  __syncthreads();
  if (wn == 0) {
    float t0 = ls0 + stgL[wm * 16 + r];
    float t1 = ls1 + stgL[wm * 16 + r + 8];
    t0 = __shfl_sync(0xffffffffu, t0, lane & ~3u);
    t1 = __shfl_sync(0xffffffffu, t1, lane & ~3u);
    float inv0 = 1.0f / t0;
    float inv1 = 1.0f / t1;
#pragma unroll
    for (int nt = 0; nt < 8; nt++) {
      int c = nt * 8 + 2 * qd;
      float2 a0 = *(float2*)&stgO[(wm * 16 + r) * 64 + c];
      float2 a1 = *(float2*)&stgO[(wm * 16 + r + 8) * 64 + c];
      *(float2*)&out[(qtok0 + wm * 16 + r) * 64 + c] =
          make_float2((o[nt][0] + a0.x) * inv0, (o[nt][1] + a0.y) * inv0);
      *(float2*)&out[(qtok0 + wm * 16 + r + 8) * 64 + c] =
          make_float2((o[nt][2] + a1.x) * inv1, (o[nt][3] + a1.y) * inv1);
    }
  }
}

// ---------------------------------------------------------------------------
extern "C" void kernel_launch(void* const* d_in, const int* in_sizes, int n_in,
                              void* d_out, int out_size) {
  const float* Q = (const float*)d_in[0];
  const float* K = (const float*)d_in[1];
  const float* V = (const float*)d_in[2];
  const float* Wq = (const float*)d_in[3];
  const float* bq = (const float*)d_in[4];
  const float* Wk = (const float*)d_in[5];
  const float* bk = (const float*)d_in[6];
  const float* Wv = (const float*)d_in[7];
  const float* bv = (const float*)d_in[8];
  // d_in[9]: causal mask -- applied analytically in-kernel.

  cudaFuncSetAttribute(proj_mma, cudaFuncAttributeMaxDynamicSharedMemorySize,
                       P_SMEM);
  cudaFuncSetAttribute(attn_mma, cudaFuncAttributeMaxDynamicSharedMemorySize,
                       A_SMEM);

  wconv<<<192, 256>>>(Wq, Wk, Wv);
  proj_mma<<<256, 256, P_SMEM>>>(Q, K, V, bq, bk, bv);
  attn_mma<<<dim3(128, BB), 128, A_SMEM>>>((float*)d_out);
}

// round 16
// speedup vs baseline: 1.5826x; 1.5826x over previous
#include <cuda_runtime.h>
#include <cuda_fp16.h>
#include <stdint.h>

#define BB 4
#define LL 4096
#define DD 1024
#define DKK 64
#define BL (BB * LL)

// Projected operands, single fp16.
// q/k: [token][64] row-major (q pre-scaled by 0.125*log2e). v: [dk][token].
__device__ __half g_q[(size_t)BL * 64];
__device__ __half g_k[(size_t)BL * 64];
__device__ __half g_v[(size_t)64 * BL];
// Pre-converted weights fp16: [which][n][k], k contiguous.
__device__ __half g_w[3 * 64 * 1024];

// ---------------------------------------------------------------------------
// helpers
// ---------------------------------------------------------------------------
__device__ __forceinline__ uint32_t smem_u32(const void* p) {
  uint32_t a;
  asm("{ .reg .u64 t; cvta.to.shared.u64 t, %1; cvt.u32.u64 %0, t; }"
      : "=r"(a) : "l"(p));
  return a;
}
__device__ __forceinline__ void sts128(uint32_t a, uint4 v) {
  asm volatile("st.shared.v4.b32 [%0], {%1,%2,%3,%4};" ::"r"(a), "r"(v.x),
               "r"(v.y), "r"(v.z), "r"(v.w));
}
__device__ __forceinline__ float2 lds64f(uint32_t a) {
  float2 v;
  asm volatile("ld.shared.v2.f32 {%0,%1}, [%2];" : "=f"(v.x), "=f"(v.y)
               : "r"(a));
  return v;
}
__device__ __forceinline__ void cpa16(uint32_t dst, const void* src) {
  asm volatile("cp.async.cg.shared.global [%0], [%1], 16;" ::"r"(dst),
               "l"(__cvta_generic_to_global(src))
               : "memory");
}
#define CP_COMMIT() asm volatile("cp.async.commit_group;" ::: "memory")
#define CP_WAIT0() asm volatile("cp.async.wait_group 0;" ::: "memory")
#define CP_WAIT1() asm volatile("cp.async.wait_group 1;" ::: "memory")

__device__ __forceinline__ void ldmx4(uint32_t a, uint32_t& r0, uint32_t& r1,
                                      uint32_t& r2, uint32_t& r3) {
  asm volatile("ldmatrix.sync.aligned.m8n8.x4.shared.b16 {%0,%1,%2,%3}, [%4];"
               : "=r"(r0), "=r"(r1), "=r"(r2), "=r"(r3) : "r"(a));
}
__device__ __forceinline__ void ldmx2(uint32_t a, uint32_t& r0, uint32_t& r1) {
  asm volatile("ldmatrix.sync.aligned.m8n8.x2.shared.b16 {%0,%1}, [%2];"
               : "=r"(r0), "=r"(r1) : "r"(a));
}
__device__ __forceinline__ void mma16816(float c[4], const uint32_t a[4],
                                         const uint32_t b0, const uint32_t b1) {
  asm volatile(
      "mma.sync.aligned.m16n8k16.row.col.f32.f16.f16.f32 "
      "{%0,%1,%2,%3}, {%4,%5,%6,%7}, {%8,%9}, {%0,%1,%2,%3};"
      : "+f"(c[0]), "+f"(c[1]), "+f"(c[2]), "+f"(c[3])
      : "r"(a[0]), "r"(a[1]), "r"(a[2]), "r"(a[3]), "r"(b0), "r"(b1));
}
__device__ __forceinline__ float ex2(float x) {
  float r;
  asm("ex2.approx.f32 %0, %1;" : "=f"(r) : "f"(x));
  return r;
}
// pack two floats into fp16x2 (x0 low, x1 high).
__device__ __forceinline__ uint32_t pkhf(float x0, float x1) {
  __half2 h = __floats2half2_rn(x0, x1);
  return *(uint32_t*)&h;
}

// ---------------------------------------------------------------------------
// Weight pre-convert: W[which][k][n] fp32 -> g_w [which][n][k] fp16.
// ---------------------------------------------------------------------------
__global__ __launch_bounds__(256) void wconv(const float* __restrict__ Wq,
                                             const float* __restrict__ Wk,
                                             const float* __restrict__ Wv) {
  __shared__ float tile[16][65];
  const int which = blockIdx.x >> 6;
  const int k0 = (blockIdx.x & 63) * 16;
  const float* W = (which == 0) ? Wq : (which == 1) ? Wk : Wv;
  const int tid = threadIdx.x;
#pragma unroll
  for (int i = 0; i < 4; i++) {
    int id = tid + 256 * i;  // 0..1023
    int kk = id >> 6, n = id & 63;
    tile[kk][n] = W[(size_t)(k0 + kk) * DKK + n];
  }
  __syncthreads();
#pragma unroll
  for (int i = 0; i < 4; i++) {
    int id = tid + 256 * i;
    int n = id >> 4, kk = id & 15;
    g_w[which * 65536 + n * 1024 + k0 + kk] = __float2half(tile[kk][n]);
  }
}

// ---------------------------------------------------------------------------
// FUSED projection, 256 threads (8 warps = 4 m-groups x 2 n-halves).
// q/k/v[m,n] = X_w[m,:]·W_w[:,n] + b_w.  Each X read once.
// Grid 256: CTA = 64 token rows; warp tile 16m x 32n per which.
// Double buffer, prefetch 1 (wait0 -> sync -> issue -> compute).
// Stage = 3 X tiles (64x144 B fp32) + 3 W tiles (64x80 B fp16) = 43008.
// ---------------------------------------------------------------------------
#define PXS 9216
#define PWS 5120
#define PSTG (3 * PXS + 3 * PWS)  // 43008
#define P_SMEM (2 * PSTG)         // 86016

__global__ __launch_bounds__(256, 2) void proj_mma(
    const float* __restrict__ Q, const float* __restrict__ K,
    const float* __restrict__ V, const float* __restrict__ bq,
    const float* __restrict__ bk, const float* __restrict__ bv) {
  extern __shared__ __align__(16) char smem[];
  const uint32_t sb = smem_u32(smem);
  const int tid = threadIdx.x, wid = tid >> 5, lane = tid & 31;
  const int wm = wid & 3, wn = wid >> 2;
  const int r = lane >> 2, qd = lane & 3;
  const int g = lane >> 3;  // ldmatrix x4 group
  const int m0 = blockIdx.x * 64;

  const float* Xs[3] = {Q, K, V};
  const float* biases[3] = {bq, bk, bv};

  float acc[3][4][4];
#pragma unroll
  for (int w = 0; w < 3; w++)
#pragma unroll
    for (int nt = 0; nt < 4; nt++)
#pragma unroll
      for (int i = 0; i < 4; i++) acc[w][nt][i] = 0.0f;

  auto stage_load = [&](uint32_t st, int k0) {
#pragma unroll
    for (int i = 0; i < 9; i++) {
      int idx = tid + 256 * i;  // 0..2303
      if (idx < 1536) {
        int w = idx >> 9;
        int id = idx & 511;
        int row = id >> 3, c = id & 7;
        cpa16(st + w * PXS + row * 144 + c * 16,
              Xs[w] + (size_t)(m0 + row) * DD + k0 + c * 4);
      } else {
        int id = idx - 1536;  // 0..767
        int w = id >> 8;
        int rem = id & 255;
        int row = rem >> 2, c = rem & 3;
        cpa16(st + 3 * PXS + w * PWS + row * 80 + c * 16,
              g_w + w * 65536 + row * 1024 + k0 + c * 8);
      }
    }
  };

  stage_load(sb, 0);
  CP_COMMIT();

  for (int kc = 0; kc < 32; kc++) {
    CP_WAIT0();       // stage kc&1 fully landed
    __syncthreads();  // all warps done reading stage (kc+1)&1 from iter kc-1
    if (kc + 1 < 32) {
      stage_load(sb + ((kc + 1) & 1) * PSTG, (kc + 1) * 32);
      CP_COMMIT();
    }
    const uint32_t st = sb + (kc & 1) * PSTG;
#pragma unroll
    for (int ks = 0; ks < 2; ks++) {
#pragma unroll
      for (int w = 0; w < 3; w++) {
        uint32_t ah[4];
        {
          uint32_t a0 =
              st + w * PXS + (wm * 16 + r) * 144 + (ks * 16 + 2 * qd) * 4;
          float2 v0 = lds64f(a0);
          float2 v1 = lds64f(a0 + 8 * 144);
          float2 v2 = lds64f(a0 + 32);
          float2 v3 = lds64f(a0 + 8 * 144 + 32);
          ah[0] = pkhf(v0.x, v0.y);
          ah[1] = pkhf(v1.x, v1.y);
          ah[2] = pkhf(v2.x, v2.y);
          ah[3] = pkhf(v3.x, v3.y);
        }
        // W fragments: one ldmx4 covers two adjacent 8-col n-tiles.
#pragma unroll
        for (int ntp = 0; ntp < 2; ntp++) {
          uint32_t bb = st + 3 * PXS + w * PWS +
                        (wn * 32 + ntp * 16 + (g >> 1) * 8 + (lane & 7)) * 80 +
                        ks * 32 + (g & 1) * 16;
          uint32_t b0, b1, b2, b3;
          ldmx4(bb, b0, b1, b2, b3);
          mma16816(acc[w][2 * ntp], ah, b0, b1);
          mma16816(acc[w][2 * ntp + 1], ah, b2, b3);
        }
      }
    }
  }

  // Epilogue: bias, (scale for q), fp16 store.  Columns wn*32 .. wn*32+31.
  const int tok0 = m0 + wm * 16 + r;
#pragma unroll
  for (int w = 0; w < 3; w++) {
    const float scl = (w == 0) ? 0.125f * 1.4426950408889634f : 1.0f;
    const float* bias = biases[w];
#pragma unroll
    for (int nt = 0; nt < 4; nt++) {
      int c = wn * 32 + nt * 8 + 2 * qd;
      float bz0 = bias[c], bz1 = bias[c + 1];
      float v0 = (acc[w][nt][0] + bz0) * scl;
      float v1 = (acc[w][nt][1] + bz1) * scl;
      float v2 = (acc[w][nt][2] + bz0) * scl;
      float v3 = (acc[w][nt][3] + bz1) * scl;
      if (w < 2) {
        __half* o = (w == 0) ? g_q : g_k;
        *(uint32_t*)&o[(size_t)tok0 * 64 + c] = pkhf(v0, v1);
        *(uint32_t*)&o[(size_t)(tok0 + 8) * 64 + c] = pkhf(v2, v3);
      } else {
        g_v[(size_t)c * BL + tok0] = __float2half(v0);
        g_v[(size_t)(c + 1) * BL + tok0] = __float2half(v1);
        g_v[(size_t)c * BL + tok0 + 8] = __float2half(v2);
        g_v[(size_t)(c + 1) * BL + tok0 + 8] = __float2half(v3);
      }
    }
  }
}

// ---------------------------------------------------------------------------
// Causal flash attention (fp16 HMMA), cp.async 3-stage ring (prefetch 2).
// EXACT R14 configuration (occ 3 -- no register cap / no spills).
// Grid (128,4) x 128 thr; CTA = ONE 32-row q tile, t = 127 - x (LPT);
// 512 CTAs at 3/SM. Diagonal peeled. lsum via ones-column of V^T (o[8]).
// smem: q@0 (4608); stages @4608+s*19584: K 64x144, V 72x144.
// ---------------------------------------------------------------------------
#define AP 144
#define SQ 0
#define STAGE0 4608
#define ST_V 9216
#define STAGE_STRIDE 19584
#define A_SMEM (4608 + 3 * 19584)
#define STG_O 4608
#define STG_L (4608 + 8192)

__device__ __forceinline__ void load_kv_async(uint32_t stg, size_t kt0,
                                              int tid) {
#pragma unroll
  for (int i = 0; i < 8; i++) {
    int idx = tid + 128 * i;  // 0..1023
    int arr = idx >> 9;       // 0: K, 1: V
    int id = idx & 511;
    int rr = id >> 3, c8 = id & 7;
    uint32_t dst = stg + arr * ST_V + rr * AP + c8 * 16;
    const __half* src = (arr == 0) ? (g_k + (kt0 + rr) * 64 + c8 * 8)
                                   : (g_v + (size_t)rr * BL + kt0 + c8 * 8);
    cpa16(dst, src);
  }
}

__global__ __launch_bounds__(128, 3) void attn_mma(float* __restrict__ out) {
  extern __shared__ __align__(16) char smem[];
  const uint32_t sb = smem_u32(smem);
  const int tid = threadIdx.x, wid = tid >> 5, lane = tid & 31;
  const int wm = wid & 1, wn = wid >> 1;
  const int r = lane >> 2, qd = lane & 3;
  const int b = blockIdx.y;
  const int t = 127 - blockIdx.x;  // largest tiles scheduled first (LPT)
  const int jmax = t >> 1;
  const size_t qtok0 = (size_t)b * LL + t * 32;
  const size_t bt0 = (size_t)b * LL;
  const int g = lane >> 3;  // ldmatrix x4 group

  // q tile (32 rows) -> smem
#pragma unroll
  for (int i = 0; i < 2; i++) {
    int id = tid + 128 * i;
    int rr = id >> 3, c8 = id & 7;
    sts128(sb + SQ + rr * AP + c8 * 16,
           *(const uint4*)&g_q[(qtok0 + rr) * 64 + c8 * 8]);
  }
  // ones/zeros rows 64-71 of all 3 V stages (lsum column; never overwritten)
  for (int idx = tid; idx < 3 * 8 * 36; idx += 128) {
    int s = idx / (8 * 36);
    int rem = idx % (8 * 36);
    int rr = rem / 36, c = rem % 36;
    *(uint32_t*)(smem + STAGE0 + s * STAGE_STRIDE + ST_V + (64 + rr) * AP +
                 c * 4) = (rr == 0) ? 0x3C003C00u : 0u;
  }
  load_kv_async(sb + STAGE0, bt0, tid);
  CP_COMMIT();
  if (jmax >= 1) load_kv_async(sb + STAGE0 + STAGE_STRIDE, bt0 + 64, tid);
  CP_COMMIT();
  __syncthreads();  // q + ones visible

  // q fragments (held in regs all kernel)
  uint32_t qa[4][4];
#pragma unroll
  for (int ks = 0; ks < 4; ks++) {
    uint32_t ab =
        sb + SQ + (wm * 16 + (lane & 15)) * AP + ks * 32 + (lane >> 4) * 16;
    ldmx4(ab, qa[ks][0], qa[ks][1], qa[ks][2], qa[ks][3]);
  }

  float o[9][4];
#pragma unroll
  for (int nt = 0; nt < 9; nt++)
#pragma unroll
    for (int i = 0; i < 4; i++) o[nt][i] = 0.0f;

  auto body = [&](int j, bool diag) {
    const uint32_t stg = sb + STAGE0 + (j % 3) * STAGE_STRIDE;
    const uint32_t sk = stg, sv = stg + ST_V;

    float s[4][4];
#pragma unroll
    for (int nt = 0; nt < 4; nt++)
#pragma unroll
      for (int i = 0; i < 4; i++) s[nt][i] = 0.0f;
#pragma unroll
    for (int ks = 0; ks < 4; ks++) {
#pragma unroll
      for (int ntp = 0; ntp < 2; ntp++) {
        uint32_t bb = sk +
                      (wn * 32 + ntp * 16 + (g >> 1) * 8 + (lane & 7)) * AP +
                      ks * 32 + (g & 1) * 16;
        uint32_t b0, b1, b2, b3;
        ldmx4(bb, b0, b1, b2, b3);
        mma16816(s[2 * ntp], qa[ks], b0, b1);
        mma16816(s[2 * ntp + 1], qa[ks], b2, b3);
      }
    }

    const int rg0 = t * 32 + wm * 16 + r, rg1 = rg0 + 8;
    uint32_t pa[2][4];
#pragma unroll
    for (int nt = 0; nt < 4; nt++) {
      float e0 = ex2(s[nt][0]);
      float e1 = ex2(s[nt][1]);
      float e2 = ex2(s[nt][2]);
      float e3 = ex2(s[nt][3]);
      if (diag) {
        int cg = j * 64 + wn * 32 + nt * 8 + 2 * qd;
        if (cg > rg0) e0 = 0.0f;
        if (cg + 1 > rg0) e1 = 0.0f;
        if (cg > rg1) e2 = 0.0f;
        if (cg + 1 > rg1) e3 = 0.0f;
      }
      int k2 = nt >> 1, h2 = (nt & 1) * 2;
      pa[k2][h2] = pkhf(e0, e1);
      pa[k2][h2 + 1] = pkhf(e2, e3);
    }

#pragma unroll
    for (int k2 = 0; k2 < 2; k2++) {
#pragma unroll
      for (int ntp = 0; ntp < 4; ntp++) {
        uint32_t bb = sv + (ntp * 16 + (g >> 1) * 8 + (lane & 7)) * AP +
                      (wn * 32 + k2 * 16) * 2 + (g & 1) * 16;
        uint32_t b0, b1, b2, b3;
        ldmx4(bb, b0, b1, b2, b3);
        mma16816(o[2 * ntp], pa[k2], b0, b1);
        mma16816(o[2 * ntp + 1], pa[k2], b2, b3);
      }
      uint32_t bb1 = sv + (64 + (lane & 7)) * AP + (wn * 32 + k2 * 16) * 2 +
                     ((lane >> 3) & 1) * 16;
      uint32_t c0, c1;
      ldmx2(bb1, c0, c1);
      mma16816(o[8], pa[k2], c0, c1);
    }
  };

  for (int j = 0; j < jmax; j++) {
    CP_WAIT1();       // in-order completion: stage j ready
    __syncthreads();  // all warps past body(j-1); slot (j+2)%3 reusable
    if (j + 2 <= jmax)
      load_kv_async(sb + STAGE0 + ((j + 2) % 3) * STAGE_STRIDE,
                    bt0 + (size_t)(j + 2) * 64, tid);
    CP_COMMIT();  // always commit (possibly empty)
    body(j, false);
  }
  CP_WAIT1();
  __syncthreads();
  CP_COMMIT();
  body(jmax, true);  // diagonal tile, masked
  __syncthreads();   // all compute done; stage smem reusable for epilogue

  // epilogue: combine key-halves via smem; lsum from o[8] (col 64, qd==0).
  float ls0 = o[8][0], ls1 = o[8][2];
  float* stgO = (float*)(smem + STG_O);
  float* stgL = (float*)(smem + STG_L);
  if (wn == 1) {
    if (qd == 0) {
      stgL[wm * 16 + r] = ls0;
      stgL[wm * 16 + r + 8] = ls1;
    }
#pragma unroll
    for (int nt = 0; nt < 8; nt++) {
      int c = nt * 8 + 2 * qd;
      *(float2*)&stgO[(wm * 16 + r) * 64 + c] = make_float2(o[nt][0], o[nt][1]);
      *(float2*)&stgO[(wm * 16 + r + 8) * 64 + c] =
          make_float2(o[nt][2], o[nt][3]);
    }
  }
  __syncthreads();
  if (wn == 0) {
    float t0 = ls0 + stgL[wm * 16 + r];
    float t1 = ls1 + stgL[wm * 16 + r + 8];
    t0 = __shfl_sync(0xffffffffu, t0, lane & ~3u);
    t1 = __shfl_sync(0xffffffffu, t1, lane & ~3u);
    float inv0 = 1.0f / t0;
    float inv1 = 1.0f / t1;
#pragma unroll
    for (int nt = 0; nt < 8; nt++) {
      int c = nt * 8 + 2 * qd;
      float2 a0 = *(float2*)&stgO[(wm * 16 + r) * 64 + c];
      float2 a1 = *(float2*)&stgO[(wm * 16 + r + 8) * 64 + c];
      *(float2*)&out[(qtok0 + wm * 16 + r) * 64 + c] =
          make_float2((o[nt][0] + a0.x) * inv0, (o[nt][1] + a0.y) * inv0);
      *(float2*)&out[(qtok0 + wm * 16 + r + 8) * 64 + c] =
          make_float2((o[nt][2] + a1.x) * inv1, (o[nt][3] + a1.y) * inv1);
    }
  }
}

// ---------------------------------------------------------------------------
extern "C" void kernel_launch(void* const* d_in, const int* in_sizes, int n_in,
                              void* d_out, int out_size) {
  const float* Q = (const float*)d_in[0];
  const float* K = (const float*)d_in[1];
  const float* V = (const float*)d_in[2];
  const float* Wq = (const float*)d_in[3];
  const float* bq = (const float*)d_in[4];
  const float* Wk = (const float*)d_in[5];
  const float* bk = (const float*)d_in[6];
  const float* Wv = (const float*)d_in[7];
  const float* bv = (const float*)d_in[8];
  // d_in[9]: causal mask -- applied analytically in-kernel.

  cudaFuncSetAttribute(proj_mma, cudaFuncAttributeMaxDynamicSharedMemorySize,
                       P_SMEM);
  cudaFuncSetAttribute(attn_mma, cudaFuncAttributeMaxDynamicSharedMemorySize,
                       A_SMEM);

  wconv<<<192, 256>>>(Wq, Wk, Wv);
  proj_mma<<<256, 256, P_SMEM>>>(Q, K, V, bq, bk, bv);
  attn_mma<<<dim3(128, BB), 128, A_SMEM>>>((float*)d_out);
}